// round 3
// baseline (speedup 1.0000x reference)
#include <cuda_runtime.h>
#include <cstdint>

// ---------------------------------------------------------------------------
// SymmetrizeRotavg:
//   scaled[n]   = inv_lat[b(n)]^T @ forces[n]
//   acc[symm_map[n,o]] += rot[o] @ scaled[n]   (o = 0..O-1)
//   out[n]      = lat[b(n)]^T @ (acc[n] / O)
//
// The scatter is pinned at the REDG per-lane floor (50.3M red.v4 lanes x
// ~1.29 cyc/lane / 148 SMs). Everything else is shaved to stay under that
// shadow: fused init (scaled + zero), templated division, float4 LDS for
// rot, evict-first streaming of symm_map.
// ---------------------------------------------------------------------------

#define MAX_N (1 << 20)   // N = 1,048,576 for this problem
#define MAX_O 64

__device__ float4 g_scaled[MAX_N];
__device__ float4 g_acc[MAX_N];

// ---------------------------------------------------------------------------
// Init: scaled = inv_lat^T f and acc = 0, 4 atoms per thread (A % 4 == 0 so
// all 4 atoms share one lattice; forces read as 3x float4).
// ---------------------------------------------------------------------------
__global__ __launch_bounds__(256) void k_init4(
    const float* __restrict__ inv_lat,   // (B,3,3)
    const float* __restrict__ forces,    // (N,3)
    int N4, int A)
{
    int q = blockIdx.x * blockDim.x + threadIdx.x;
    if (q >= N4) return;
    int n0 = q * 4;
    int b = n0 / A;

    const float4* f4 = reinterpret_cast<const float4*>(forces + (long long)n0 * 3);
    float4 a = f4[0];   // f0.x f0.y f0.z f1.x
    float4 c = f4[1];   // f1.y f1.z f2.x f2.y
    float4 d = f4[2];   // f2.z f3.x f3.y f3.z

    const float* M = inv_lat + 9 * b;   // M[j*3+i]
    float M00 = __ldg(M + 0), M01 = __ldg(M + 1), M02 = __ldg(M + 2);
    float M10 = __ldg(M + 3), M11 = __ldg(M + 4), M12 = __ldg(M + 5);
    float M20 = __ldg(M + 6), M21 = __ldg(M + 7), M22 = __ldg(M + 8);

    float fx[4] = { a.x, a.w, c.z, d.y };
    float fy[4] = { a.y, c.x, c.w, d.z };
    float fz[4] = { a.z, c.y, d.x, d.w };

    float4 zero = make_float4(0.f, 0.f, 0.f, 0.f);
#pragma unroll
    for (int t = 0; t < 4; t++) {
        float sx = M00 * fx[t] + M10 * fy[t] + M20 * fz[t];
        float sy = M01 * fx[t] + M11 * fy[t] + M21 * fz[t];
        float sz = M02 * fx[t] + M12 * fy[t] + M22 * fz[t];
        g_scaled[n0 + t] = make_float4(sx, sy, sz, 0.0f);
        g_acc[n0 + t]    = zero;
    }
}

// Scalar fallback init.
__global__ __launch_bounds__(256) void k_init1(
    const float* __restrict__ inv_lat,
    const float* __restrict__ forces,
    int N, int A)
{
    int n = blockIdx.x * blockDim.x + threadIdx.x;
    if (n >= N) return;
    int b = n / A;
    float f0 = forces[3 * n + 0];
    float f1 = forces[3 * n + 1];
    float f2 = forces[3 * n + 2];
    const float* M = inv_lat + 9 * b;
    float sx = M[0] * f0 + M[3] * f1 + M[6] * f2;
    float sy = M[1] * f0 + M[4] * f1 + M[7] * f2;
    float sz = M[2] * f0 + M[5] * f1 + M[8] * f2;
    g_scaled[n] = make_float4(sx, sy, sz, 0.0f);
    g_acc[n]    = make_float4(0.f, 0.f, 0.f, 0.f);
}

__device__ __forceinline__ void red_add_v4(float4* p, float x, float y, float z)
{
    asm volatile(
        "{\n\t"
        ".reg .u64 ga;\n\t"
        "cvta.to.global.u64 ga, %0;\n\t"
        "red.global.add.v4.f32 [ga], {%1, %2, %3, %4};\n\t"
        "}"
        :: "l"(p), "f"(x), "f"(y), "f"(z), "f"(0.0f)
        : "memory");
}

__device__ __forceinline__ int4 ldcs_int4(const int* p)
{
    int4 v;
    asm volatile("ld.global.cs.v4.s32 {%0,%1,%2,%3}, [%4];"
                 : "=r"(v.x), "=r"(v.y), "=r"(v.z), "=r"(v.w)
                 : "l"(p));
    return v;
}

// ---------------------------------------------------------------------------
// Scatter: one thread = one n and 4 consecutive ops. PER_N is a compile-time
// constant so n = idx / PER_N compiles to a mul-shift. rot rows live in smem
// as padded float4 so every rot access is a single LDS.128.
// ---------------------------------------------------------------------------
template<int PER_N>
__global__ __launch_bounds__(256) void k_scatter(
    const float* __restrict__ gops,   // (O,4,4)
    const int*   __restrict__ smap,   // (N,O)
    int N, int O)
{
    __shared__ float4 srot[MAX_O * 3];   // per op: 3 rows, each (Ri0,Ri1,Ri2,0)
    for (int t = threadIdx.x; t < O * 3; t += blockDim.x) {
        int o = t / 3;
        int i = t - o * 3;
        srot[t] = make_float4(gops[o * 16 + i * 4 + 0],
                              gops[o * 16 + i * 4 + 1],
                              gops[o * 16 + i * 4 + 2], 0.0f);
    }
    __syncthreads();

    long long idx = (long long)blockIdx.x * blockDim.x + threadIdx.x;
    long long total = (long long)N * PER_N;
    if (idx >= total) return;
    int n = (int)(idx / PER_N);           // compile-time divisor -> mul-shift
    int k = (int)(idx - (long long)n * PER_N);

    float4 s = g_scaled[n];
    int4 t4 = ldcs_int4(smap + (long long)n * O + k * 4);
    int tgt[4] = { t4.x, t4.y, t4.z, t4.w };

#pragma unroll
    for (int r = 0; r < 4; r++) {
        int o = k * 4 + r;
        float4 r0 = srot[o * 3 + 0];
        float4 r1 = srot[o * 3 + 1];
        float4 r2 = srot[o * 3 + 2];
        float x = r0.x * s.x + r0.y * s.y + r0.z * s.z;
        float y = r1.x * s.x + r1.y * s.y + r1.z * s.z;
        float z = r2.x * s.x + r2.y * s.y + r2.z * s.z;
        red_add_v4(&g_acc[tgt[r]], x, y, z);
    }
}

// General fallback: one thread per (n,o), runtime O.
__global__ __launch_bounds__(256) void k_scatter_gen(
    const float* __restrict__ gops,
    const int*   __restrict__ smap,
    int N, int O)
{
    __shared__ float4 srot[MAX_O * 3];
    for (int t = threadIdx.x; t < O * 3; t += blockDim.x) {
        int o = t / 3;
        int i = t - o * 3;
        srot[t] = make_float4(gops[o * 16 + i * 4 + 0],
                              gops[o * 16 + i * 4 + 1],
                              gops[o * 16 + i * 4 + 2], 0.0f);
    }
    __syncthreads();

    long long idx = (long long)blockIdx.x * blockDim.x + threadIdx.x;
    long long total = (long long)N * O;
    if (idx >= total) return;
    int n = (int)(idx / O);
    int o = (int)(idx - (long long)n * O);

    float4 s = g_scaled[n];
    int tgt = smap[(long long)n * O + o];
    float4 r0 = srot[o * 3 + 0];
    float4 r1 = srot[o * 3 + 1];
    float4 r2 = srot[o * 3 + 2];
    float x = r0.x * s.x + r0.y * s.y + r0.z * s.z;
    float y = r1.x * s.x + r1.y * s.y + r1.z * s.z;
    float z = r2.x * s.x + r2.y * s.y + r2.z * s.z;
    red_add_v4(&g_acc[tgt], x, y, z);
}

// ---------------------------------------------------------------------------
// Final: out = lat^T (acc / O), 4 atoms per thread, float4 stores.
// ---------------------------------------------------------------------------
__global__ __launch_bounds__(256) void k_final4(
    const float* __restrict__ lat,
    float* __restrict__ out,
    int N4, int A, float inv_count)
{
    int q = blockIdx.x * blockDim.x + threadIdx.x;
    if (q >= N4) return;
    int n0 = q * 4;
    int b = n0 / A;
    const float* L = lat + 9 * b;
    float L00 = __ldg(L + 0), L01 = __ldg(L + 1), L02 = __ldg(L + 2);
    float L10 = __ldg(L + 3), L11 = __ldg(L + 4), L12 = __ldg(L + 5);
    float L20 = __ldg(L + 6), L21 = __ldg(L + 7), L22 = __ldg(L + 8);

    float r[12];
#pragma unroll
    for (int t = 0; t < 4; t++) {
        float4 a = g_acc[n0 + t];
        float s0 = a.x * inv_count;
        float s1 = a.y * inv_count;
        float s2 = a.z * inv_count;
        r[t * 3 + 0] = L00 * s0 + L10 * s1 + L20 * s2;
        r[t * 3 + 1] = L01 * s0 + L11 * s1 + L21 * s2;
        r[t * 3 + 2] = L02 * s0 + L12 * s1 + L22 * s2;
    }
    float4* dst = reinterpret_cast<float4*>(out + (long long)q * 12);
    dst[0] = make_float4(r[0], r[1], r[2],  r[3]);
    dst[1] = make_float4(r[4], r[5], r[6],  r[7]);
    dst[2] = make_float4(r[8], r[9], r[10], r[11]);
}

__global__ __launch_bounds__(256) void k_final1(
    const float* __restrict__ lat,
    float* __restrict__ out,
    int N, int A, float inv_count)
{
    int n = blockIdx.x * blockDim.x + threadIdx.x;
    if (n >= N) return;
    int b = n / A;
    float4 a = g_acc[n];
    float s0 = a.x * inv_count;
    float s1 = a.y * inv_count;
    float s2 = a.z * inv_count;
    const float* L = lat + 9 * b;
    out[3 * n + 0] = L[0] * s0 + L[3] * s1 + L[6] * s2;
    out[3 * n + 1] = L[1] * s0 + L[4] * s1 + L[7] * s2;
    out[3 * n + 2] = L[2] * s0 + L[5] * s1 + L[8] * s2;
}

extern "C" void kernel_launch(void* const* d_in, const int* in_sizes, int n_in,
                              void* d_out, int out_size)
{
    const float* lattices     = (const float*)d_in[0];  // (B,3,3)
    const float* inv_lattices = (const float*)d_in[1];  // (B,3,3)
    const float* forces       = (const float*)d_in[2];  // (N,3)
    // d_in[3] = num_atoms (int64, uniform A)
    const float* general_ops  = (const float*)d_in[4];  // (O,4,4)
    const int*   symm_map     = (const int*)d_in[5];    // (N,O)
    // d_in[6] = num_general_ops (int64, uniform O)

    int B = in_sizes[0] / 9;
    int N = in_sizes[2] / 3;
    int O = in_sizes[4] / 16;
    int A = N / B;

    float* out = (float*)d_out;
    const int TPB = 256;
    bool vec_ok = ((A & 3) == 0) && ((N & 3) == 0);

    // Init: scaled + zero acc
    if (vec_ok) {
        int N4 = N / 4;
        k_init4<<<(N4 + TPB - 1) / TPB, TPB>>>(inv_lattices, forces, N4, A);
    } else {
        k_init1<<<(N + TPB - 1) / TPB, TPB>>>(inv_lattices, forces, N, A);
    }

    // Scatter
    if (O == 48) {
        long long total = (long long)N * 12;
        int blocks = (int)((total + TPB - 1) / TPB);
        k_scatter<12><<<blocks, TPB>>>(general_ops, symm_map, N, O);
    } else if ((O & 3) == 0 && O == 32) {
        long long total = (long long)N * 8;
        int blocks = (int)((total + TPB - 1) / TPB);
        k_scatter<8><<<blocks, TPB>>>(general_ops, symm_map, N, O);
    } else if ((O & 3) == 0 && O == 64) {
        long long total = (long long)N * 16;
        int blocks = (int)((total + TPB - 1) / TPB);
        k_scatter<16><<<blocks, TPB>>>(general_ops, symm_map, N, O);
    } else {
        long long total = (long long)N * O;
        int blocks = (int)((total + TPB - 1) / TPB);
        k_scatter_gen<<<blocks, TPB>>>(general_ops, symm_map, N, O);
    }

    // Final
    float inv_count = 1.0f / (float)O;
    if (vec_ok) {
        int N4 = N / 4;
        k_final4<<<(N4 + TPB - 1) / TPB, TPB>>>(lattices, out, N4, A, inv_count);
    } else {
        k_final1<<<(N + TPB - 1) / TPB, TPB>>>(lattices, out, N, A, inv_count);
    }
}

// round 4
// speedup vs baseline: 1.6530x; 1.6530x over previous
#include <cuda_runtime.h>
#include <cstdint>

// ---------------------------------------------------------------------------
// SymmetrizeRotavg:
//   scaled[n]   = inv_lat[b(n)]^T @ forces[n]
//   acc[symm_map[n,o]] += rot[o] @ scaled[n]   (o = 0..O-1)
//   out[n]      = lat[b(n)]^T @ (acc[n] / O)
//
// Scatter is pinned at the REDG spread floor (50.3M red.v4 lanes x 1.29
// cyc/lane / 148 SMs ~ 245us). R3 showed float4 smem rot tiles cause massive
// LDS.128 bank conflicts (addresses collapse mod 128B) -- rot MUST stay as
// scalar float smem loads. This is the R1 scatter verbatim + vectorized final.
// ---------------------------------------------------------------------------

#define MAX_N (1 << 20)   // N = 1,048,576 for this problem
#define MAX_O 64

__device__ float4 g_scaled[MAX_N];
__device__ float4 g_acc[MAX_N];

// Stage 1: scaled = inv_lat^T f ; zero the accumulator (every launch, so
// graph replays stay deterministic).
__global__ __launch_bounds__(256) void k_prep(
    const float* __restrict__ inv_lat,
    const float* __restrict__ forces,
    int N, int A)
{
    int n = blockIdx.x * blockDim.x + threadIdx.x;
    if (n >= N) return;
    int b = n / A;
    float f0 = forces[3 * n + 0];
    float f1 = forces[3 * n + 1];
    float f2 = forces[3 * n + 2];
    const float* M = inv_lat + 9 * b;   // M[j*3+i]
    float s0 = M[0] * f0 + M[3] * f1 + M[6] * f2;
    float s1 = M[1] * f0 + M[4] * f1 + M[7] * f2;
    float s2 = M[2] * f0 + M[5] * f1 + M[8] * f2;
    g_scaled[n] = make_float4(s0, s1, s2, 0.0f);
    g_acc[n]    = make_float4(0.0f, 0.0f, 0.0f, 0.0f);
}

__device__ __forceinline__ void red_add_v4(float4* p, float x, float y, float z)
{
    asm volatile(
        "{\n\t"
        ".reg .u64 ga;\n\t"
        "cvta.to.global.u64 ga, %0;\n\t"
        "red.global.add.v4.f32 [ga], {%1, %2, %3, %4};\n\t"
        "}"
        :: "l"(p), "f"(x), "f"(y), "f"(z), "f"(0.0f)
        : "memory");
}

// Stage 2 (R1 verbatim): one thread = one n and 4 consecutive ops.
// Scalar smem rot loads (bank-conflict free), plain int4 smap load.
__global__ __launch_bounds__(256) void k_scatter4(
    const float* __restrict__ gops,   // (O,4,4)
    const int*   __restrict__ smap,   // (N,O)
    int N, int O)
{
    __shared__ float srot[MAX_O * 9];
    for (int t = threadIdx.x; t < O * 9; t += blockDim.x) {
        int o = t / 9;
        int e = t - o * 9;
        int i = e / 3;
        int j = e - i * 3;
        srot[t] = gops[o * 16 + i * 4 + j];
    }
    __syncthreads();

    int per_n = O >> 2;  // groups of 4 ops (O % 4 == 0)
    long long idx = (long long)blockIdx.x * blockDim.x + threadIdx.x;
    long long total = (long long)N * per_n;
    if (idx >= total) return;
    int n = (int)(idx / per_n);
    int k = (int)(idx - (long long)n * per_n);

    float4 s = g_scaled[n];
    int4 t4 = *reinterpret_cast<const int4*>(smap + (long long)n * O + k * 4);
    int tgt[4] = { t4.x, t4.y, t4.z, t4.w };

#pragma unroll
    for (int r = 0; r < 4; r++) {
        int o = k * 4 + r;
        const float* R = srot + o * 9;   // R[i*3+j]
        float x = R[0] * s.x + R[1] * s.y + R[2] * s.z;
        float y = R[3] * s.x + R[4] * s.y + R[5] * s.z;
        float z = R[6] * s.x + R[7] * s.y + R[8] * s.z;
        red_add_v4(&g_acc[tgt[r]], x, y, z);
    }
}

// Fallback (O not a multiple of 4): one thread per (n,o).
__global__ __launch_bounds__(256) void k_scatter1(
    const float* __restrict__ gops,
    const int*   __restrict__ smap,
    int N, int O)
{
    __shared__ float srot[MAX_O * 9];
    for (int t = threadIdx.x; t < O * 9; t += blockDim.x) {
        int o = t / 9;
        int e = t - o * 9;
        int i = e / 3;
        int j = e - i * 3;
        srot[t] = gops[o * 16 + i * 4 + j];
    }
    __syncthreads();

    long long idx = (long long)blockIdx.x * blockDim.x + threadIdx.x;
    long long total = (long long)N * O;
    if (idx >= total) return;
    int n = (int)(idx / O);
    int o = (int)(idx - (long long)n * O);

    float4 s = g_scaled[n];
    int tgt = smap[(long long)n * O + o];
    const float* R = srot + o * 9;
    float x = R[0] * s.x + R[1] * s.y + R[2] * s.z;
    float y = R[3] * s.x + R[4] * s.y + R[5] * s.z;
    float z = R[6] * s.x + R[7] * s.y + R[8] * s.z;
    red_add_v4(&g_acc[tgt], x, y, z);
}

// Stage 3 vectorized: 4 atoms per thread (A % 4 == 0 so one lattice per
// thread), float4 loads of acc, 3x float4 stores of out.
__global__ __launch_bounds__(256) void k_final4(
    const float* __restrict__ lat,
    float* __restrict__ out,
    int N4, int A, float inv_count)
{
    int q = blockIdx.x * blockDim.x + threadIdx.x;
    if (q >= N4) return;
    int n0 = q * 4;
    int b = n0 / A;
    const float* L = lat + 9 * b;   // L[j*3+i]
    float L00 = __ldg(L + 0), L01 = __ldg(L + 1), L02 = __ldg(L + 2);
    float L10 = __ldg(L + 3), L11 = __ldg(L + 4), L12 = __ldg(L + 5);
    float L20 = __ldg(L + 6), L21 = __ldg(L + 7), L22 = __ldg(L + 8);

    float r[12];
#pragma unroll
    for (int t = 0; t < 4; t++) {
        float4 a = g_acc[n0 + t];
        float s0 = a.x * inv_count;
        float s1 = a.y * inv_count;
        float s2 = a.z * inv_count;
        r[t * 3 + 0] = L00 * s0 + L10 * s1 + L20 * s2;
        r[t * 3 + 1] = L01 * s0 + L11 * s1 + L21 * s2;
        r[t * 3 + 2] = L02 * s0 + L12 * s1 + L22 * s2;
    }
    float4* dst = reinterpret_cast<float4*>(out + (long long)q * 12);
    dst[0] = make_float4(r[0], r[1], r[2],  r[3]);
    dst[1] = make_float4(r[4], r[5], r[6],  r[7]);
    dst[2] = make_float4(r[8], r[9], r[10], r[11]);
}

// Scalar fallback final.
__global__ __launch_bounds__(256) void k_final1(
    const float* __restrict__ lat,
    float* __restrict__ out,
    int N, int A, float inv_count)
{
    int n = blockIdx.x * blockDim.x + threadIdx.x;
    if (n >= N) return;
    int b = n / A;
    float4 a = g_acc[n];
    float s0 = a.x * inv_count;
    float s1 = a.y * inv_count;
    float s2 = a.z * inv_count;
    const float* L = lat + 9 * b;
    out[3 * n + 0] = L[0] * s0 + L[3] * s1 + L[6] * s2;
    out[3 * n + 1] = L[1] * s0 + L[4] * s1 + L[7] * s2;
    out[3 * n + 2] = L[2] * s0 + L[5] * s1 + L[8] * s2;
}

extern "C" void kernel_launch(void* const* d_in, const int* in_sizes, int n_in,
                              void* d_out, int out_size)
{
    const float* lattices     = (const float*)d_in[0];  // (B,3,3)
    const float* inv_lattices = (const float*)d_in[1];  // (B,3,3)
    const float* forces       = (const float*)d_in[2];  // (N,3)
    // d_in[3] = num_atoms (int64, uniform A)
    const float* general_ops  = (const float*)d_in[4];  // (O,4,4)
    const int*   symm_map     = (const int*)d_in[5];    // (N,O)
    // d_in[6] = num_general_ops (int64, uniform O)

    int B = in_sizes[0] / 9;
    int N = in_sizes[2] / 3;
    int O = in_sizes[4] / 16;
    int A = N / B;

    float* out = (float*)d_out;
    const int TPB = 256;
    int blocks_n = (N + TPB - 1) / TPB;

    k_prep<<<blocks_n, TPB>>>(inv_lattices, forces, N, A);

    if ((O & 3) == 0) {
        long long total = (long long)N * (O >> 2);
        int blocks = (int)((total + TPB - 1) / TPB);
        k_scatter4<<<blocks, TPB>>>(general_ops, symm_map, N, O);
    } else {
        long long total = (long long)N * O;
        int blocks = (int)((total + TPB - 1) / TPB);
        k_scatter1<<<blocks, TPB>>>(general_ops, symm_map, N, O);
    }

    float inv_count = 1.0f / (float)O;
    if ((A & 3) == 0 && (N & 3) == 0) {
        int N4 = N / 4;
        k_final4<<<(N4 + TPB - 1) / TPB, TPB>>>(lattices, out, N4, A, inv_count);
    } else {
        k_final1<<<(N + TPB - 1) / TPB, TPB>>>(lattices, out, N, A, inv_count);
    }
}